// round 8
// baseline (speedup 1.0000x reference)
#include <cuda_runtime.h>
#include <cuda_fp16.h>
#include <stdint.h>

#define SEQT 512
#define NB   16
#define NT   512

#define S0   448    // layer0 B row stride bytes (K=96 -> 6x64B groups, padded)
#define S1   576    // layer1 B row stride bytes (K=128 -> 8x64B groups, padded)

// dynamic SMEM map (bytes)
#define OFF_B0   0                          // 2 parities x 16*448 = 14336
#define OFF_B1   14336                      // 2 parities x 16*576 = 18432
#define OFF_XA0  32768                      // exchange: 4 regions x 16 warps x 32 lanes x 16B
#define OFF_XB0  40960
#define OFF_XA1  49152
#define OFF_XB1  57344
#define SMEM_TOTAL 65536

__device__ __forceinline__ void mma_f16(float c[4], const uint32_t a[4],
                                        uint32_t b0, uint32_t b1) {
    asm volatile(
        "mma.sync.aligned.m16n8k16.row.col.f32.f16.f16.f32 "
        "{%0,%1,%2,%3}, {%4,%5,%6,%7}, {%8,%9}, {%0,%1,%2,%3};"
        : "+f"(c[0]), "+f"(c[1]), "+f"(c[2]), "+f"(c[3])
        : "r"(a[0]), "r"(a[1]), "r"(a[2]), "r"(a[3]), "r"(b0), "r"(b1));
}

__device__ __forceinline__ void split_f16(float v, uint16_t& hi, uint16_t& lo) {
    __half h = __float2half_rn(v);
    __half l = __float2half_rn(v - __half2float(h));
    hi = __half_as_ushort(h);
    lo = __half_as_ushort(l);
}

__device__ __forceinline__ float ex2f(float v) { float r; asm("ex2.approx.f32 %0, %1;" : "=f"(r) : "f"(v)); return r; }
__device__ __forceinline__ float rcpf(float v) { float r; asm("rcp.approx.f32 %0, %1;" : "=f"(r) : "f"(v)); return r; }
__device__ __forceinline__ float sigf(float x)   { return rcpf(1.0f + ex2f(-1.442695041f * x)); }
__device__ __forceinline__ float tanhf_(float x) { return fmaf(2.0f, rcpf(1.0f + ex2f(-2.885390082f * x)), -1.0f); }

// byte offset of (batch n, k) in hi/lo-interleaved B buffer
// 64B group per 16 k: [hi k0..k7-pairs | lo ...]: [hi(2k),hi(2k+1)]@((r>>1)&3)*16+((r>>3))*4? same as R7
__device__ __forceinline__ int boff(int n, int k, int S) {
    int r = k & 15;
    return n * S + (k >> 4) * 64 + ((r >> 1) & 3) * 16 + ((r >> 3) << 2) + ((r & 1) << 1);
}

__global__ void __launch_bounds__(NT, 1)
lstm_fused(const float* __restrict__ x,
           const float* __restrict__ W_ih0, const float* __restrict__ W_hh0,
           const float* __restrict__ b_ih0, const float* __restrict__ b_hh0,
           const float* __restrict__ W_ih1, const float* __restrict__ W_hh1,
           const float* __restrict__ b_ih1, const float* __restrict__ b_hh1,
           const float* __restrict__ ln_g, const float* __restrict__ ln_b,
           const float* __restrict__ fc_w, const float* __restrict__ fc_b,
           float* __restrict__ out)
{
    extern __shared__ __align__(16) unsigned char sm[];
    const int tid  = threadIdx.x;
    const int w    = tid >> 5;
    const int lane = tid & 31;
    const int g    = lane >> 2;
    const int tq   = lane & 3;
    const int wp   = w & 7;          // pair id (j-block)
    const int s    = w >> 3;         // K-half this warp computes; batch-half it updates
    const int jv   = 8 * wp + g;     // cell index this thread owns
    const int b0   = blockIdx.x * NB;

    // zero B buffers
    for (int i = tid; i < 32768 / 4; i += NT) ((uint32_t*)sm)[i] = 0;

    // ---- A fragments: BOTH gate tiles, K-half s, fp16 hi only (regs) ----
    // tile 0: gates {i,f}; tile 1: gates {g,o}.  m = tile*128 + (i&1)*64 + jv
    uint32_t A0[2][3][4], A1[2][4][4];
    #pragma unroll
    for (int tile = 0; tile < 2; tile++) {
        #pragma unroll
        for (int kt = 0; kt < 3; kt++) {
            #pragma unroll
            for (int i = 0; i < 4; i++) {
                int m = tile * 128 + (i & 1) * 64 + jv;
                int k = 48 * s + 16 * kt + 2 * tq + (i >> 1) * 8;
                float v0 = (k < 32)     ? W_ih0[m * 32 + k]     : W_hh0[m * 64 + k - 32];
                float v1 = (k + 1 < 32) ? W_ih0[m * 32 + k + 1] : W_hh0[m * 64 + k + 1 - 32];
                uint16_t h0 = __half_as_ushort(__float2half_rn(v0));
                uint16_t h1 = __half_as_ushort(__float2half_rn(v1));
                A0[tile][kt][i] = (uint32_t)h0 | ((uint32_t)h1 << 16);
            }
        }
        #pragma unroll
        for (int kt = 0; kt < 4; kt++) {
            #pragma unroll
            for (int i = 0; i < 4; i++) {
                int m = tile * 128 + (i & 1) * 64 + jv;
                int k = 64 * s + 16 * kt + 2 * tq + (i >> 1) * 8;
                float v0 = (k < 64)     ? W_ih1[m * 64 + k]     : W_hh1[m * 64 + k - 64];
                float v1 = (k + 1 < 64) ? W_ih1[m * 64 + k + 1] : W_hh1[m * 64 + k + 1 - 64];
                uint16_t h0 = __half_as_ushort(__float2half_rn(v0));
                uint16_t h1 = __half_as_ushort(__float2half_rn(v1));
                A1[tile][kt][i] = (uint32_t)h0 | ((uint32_t)h1 << 16);
            }
        }
    }

    // biases for all 4 gates at j = jv
    float bias0[4], bias1[4];
    #pragma unroll
    for (int q = 0; q < 4; q++) {
        bias0[q] = b_ih0[q * 64 + jv] + b_hh0[q * 64 + jv];
        bias1[q] = b_ih1[q * 64 + jv] + b_hh1[q * 64 + jv];
    }

    // x(0) -> B0 parity 0 (warp = batch row, lane = k)
    {
        float xv = x[((size_t)(b0 + w) * SEQT) * 32 + lane];
        uint16_t hh, hl; split_f16(xv, hh, hl);
        int o = boff(w, lane, S0);
        *(uint16_t*)(sm + OFF_B0 + o)     = hh;
        *(uint16_t*)(sm + OFF_B0 + o + 8) = hl;
    }
    __syncthreads();

    const int xsl = w * 512 + lane * 16;              // my exchange slot
    const int psl = (w ^ 8) * 512 + lane * 16;        // partner's slot
    float c0s[2] = {0, 0}, c1s[2] = {0, 0}, h1fin[2] = {0, 0};

    #pragma unroll 1
    for (int p = 0; p <= SEQT; p++) {
        const int par = p & 1;
        const unsigned char* B0r = sm + OFF_B0 + par * (NB * S0);
        const unsigned char* B1r = sm + OFF_B1 + par * (NB * S1);
        unsigned char* B0w = sm + OFF_B0 + (par ^ 1) * (NB * S0);
        unsigned char* B1w = sm + OFF_B1 + (par ^ 1) * (NB * S1);

        float xn = 0.0f;
        if (p + 1 < SEQT)
            xn = x[((size_t)(b0 + w) * SEQT + (p + 1)) * 32 + lane];

        // ===== layer0 MMA (K-half s) + send partner's batch-half partials =====
        float C0[2][2][4] = {};
        if (p < SEQT) {
            #pragma unroll
            for (int kt = 0; kt < 3; kt++) {
                #pragma unroll
                for (int nt = 0; nt < 2; nt++) {
                    uint4 v = *(const uint4*)(B0r + (8 * nt + g) * S0 + (3 * s + kt) * 64 + tq * 16);
                    mma_f16(C0[0][nt], A0[0][kt], v.x, v.y);
                    mma_f16(C0[0][nt], A0[0][kt], v.z, v.w);
                    mma_f16(C0[1][nt], A0[1][kt], v.x, v.y);
                    mma_f16(C0[1][nt], A0[1][kt], v.z, v.w);
                }
            }
            int so = s ^ 1;
            *(float4*)(sm + OFF_XA0 + xsl) = make_float4(C0[0][so][0], C0[0][so][1], C0[0][so][2], C0[0][so][3]);
            *(float4*)(sm + OFF_XB0 + xsl) = make_float4(C0[1][so][0], C0[1][so][1], C0[1][so][2], C0[1][so][3]);
        }

        // ===== layer1 MMA (K-half s) + send =====
        float C1[2][2][4] = {};
        if (p >= 1) {
            #pragma unroll
            for (int kt = 0; kt < 4; kt++) {
                #pragma unroll
                for (int nt = 0; nt < 2; nt++) {
                    uint4 v = *(const uint4*)(B1r + (8 * nt + g) * S1 + (4 * s + kt) * 64 + tq * 16);
                    mma_f16(C1[0][nt], A1[0][kt], v.x, v.y);
                    mma_f16(C1[0][nt], A1[0][kt], v.z, v.w);
                    mma_f16(C1[1][nt], A1[1][kt], v.x, v.y);
                    mma_f16(C1[1][nt], A1[1][kt], v.z, v.w);
                }
            }
            int so = s ^ 1;
            *(float4*)(sm + OFF_XA1 + xsl) = make_float4(C1[0][so][0], C1[0][so][1], C1[0][so][2], C1[0][so][3]);
            *(float4*)(sm + OFF_XB1 + xsl) = make_float4(C1[1][so][0], C1[1][so][1], C1[1][so][2], C1[1][so][3]);
        }

        asm volatile("bar.sync %0, 64;" :: "r"(1 + wp) : "memory");

        // ===== layer0 combine + activate + update =====
        if (p < SEQT) {
            float4 rA = *(const float4*)(sm + OFF_XA0 + psl);
            float4 rB = *(const float4*)(sm + OFF_XB0 + psl);
            float fa[4] = {rA.x, rA.y, rA.z, rA.w};
            float fb[4] = {rB.x, rB.y, rB.z, rB.w};
            #pragma unroll
            for (int d = 0; d < 2; d++) {
                float pi = C0[0][s][d]     + fa[d]     + bias0[0];
                float pf = C0[0][s][2 + d] + fa[2 + d] + bias0[1];
                float pg = C0[1][s][d]     + fb[d]     + bias0[2];
                float po = C0[1][s][2 + d] + fb[2 + d] + bias0[3];
                float ig = sigf(pi), fg = sigf(pf), gg = tanhf_(pg), og = sigf(po);
                float c = fg * c0s[d] + ig * gg;
                c0s[d] = c;
                float h = og * tanhf_(c);
                int b = 8 * s + 2 * tq + d;
                uint16_t hh, hl; split_f16(h, hh, hl);
                int oa = boff(b, 32 + jv, S0);
                *(uint16_t*)(B0w + oa)     = hh;   // layer0 recurrence
                *(uint16_t*)(B0w + oa + 8) = hl;
                int ob = boff(b, jv, S1);
                *(uint16_t*)(B1w + ob)     = hh;   // layer1 input
                *(uint16_t*)(B1w + ob + 8) = hl;
            }
        }

        // ===== layer1 combine + activate + update =====
        if (p >= 1) {
            float4 rA = *(const float4*)(sm + OFF_XA1 + psl);
            float4 rB = *(const float4*)(sm + OFF_XB1 + psl);
            float fa[4] = {rA.x, rA.y, rA.z, rA.w};
            float fb[4] = {rB.x, rB.y, rB.z, rB.w};
            #pragma unroll
            for (int d = 0; d < 2; d++) {
                float pi = C1[0][s][d]     + fa[d]     + bias1[0];
                float pf = C1[0][s][2 + d] + fa[2 + d] + bias1[1];
                float pg = C1[1][s][d]     + fb[d]     + bias1[2];
                float po = C1[1][s][2 + d] + fb[2 + d] + bias1[3];
                float ig = sigf(pi), fg = sigf(pf), gg = tanhf_(pg), og = sigf(po);
                float c = fg * c1s[d] + ig * gg;
                c1s[d] = c;
                float h = og * tanhf_(c);
                h1fin[d] = h;
                int b = 8 * s + 2 * tq + d;
                uint16_t hh, hl; split_f16(h, hh, hl);
                int oc = boff(b, 64 + jv, S1);
                *(uint16_t*)(B1w + oc)     = hh;   // layer1 recurrence
                *(uint16_t*)(B1w + oc + 8) = hl;
            }
        }

        if (p + 1 < SEQT) {
            uint16_t hh, hl; split_f16(xn, hh, hl);
            int o = boff(w, lane, S0);
            *(uint16_t*)(B0w + o)     = hh;
            *(uint16_t*)(B0w + o + 8) = hl;
        }
        __syncthreads();
    }

    // ---- LayerNorm + FC on h1(T-1) ----
    float* hb = (float*)(sm + OFF_XA0);
    #pragma unroll
    for (int d = 0; d < 2; d++) {
        int b = 8 * s + 2 * tq + d;
        hb[b * 64 + jv] = h1fin[d];
    }
    __syncthreads();
    if (tid < NB) {
        const float* h = hb + tid * 64;
        float mu = 0.0f;
        #pragma unroll
        for (int j = 0; j < 64; j++) mu += h[j];
        mu *= (1.0f / 64.0f);
        float var = 0.0f;
        #pragma unroll
        for (int j = 0; j < 64; j++) { float dd = h[j] - mu; var += dd * dd; }
        var *= (1.0f / 64.0f);
        float rstd = rsqrtf(var + 1e-5f);
        float sacc = 0.0f;
        #pragma unroll
        for (int j = 0; j < 64; j++)
            sacc += ((h[j] - mu) * rstd * ln_g[j] + ln_b[j]) * fc_w[j];
        out[b0 + tid] = sacc + fc_b[0];
    }
}

extern "C" void kernel_launch(void* const* d_in, const int* in_sizes, int n_in,
                              void* d_out, int out_size)
{
    const float* x     = (const float*)d_in[0];
    const float* W_ih0 = (const float*)d_in[1];
    const float* W_hh0 = (const float*)d_in[2];
    const float* b_ih0 = (const float*)d_in[3];
    const float* b_hh0 = (const float*)d_in[4];
    const float* W_ih1 = (const float*)d_in[5];
    const float* W_hh1 = (const float*)d_in[6];
    const float* b_ih1 = (const float*)d_in[7];
    const float* b_hh1 = (const float*)d_in[8];
    const float* ln_g  = (const float*)d_in[9];
    const float* ln_b  = (const float*)d_in[10];
    const float* fc_w  = (const float*)d_in[11];
    const float* fc_b  = (const float*)d_in[12];
    float* out = (float*)d_out;

    cudaFuncSetAttribute(lstm_fused, cudaFuncAttributeMaxDynamicSharedMemorySize, SMEM_TOTAL);
    lstm_fused<<<2048 / NB, NT, SMEM_TOTAL>>>(x, W_ih0, W_hh0, b_ih0, b_hh0,
                                              W_ih1, W_hh1, b_ih1, b_hh1,
                                              ln_g, ln_b, fc_w, fc_b, out);
}

// round 9
// speedup vs baseline: 1.7351x; 1.7351x over previous
#include <cuda_runtime.h>
#include <cuda_fp16.h>
#include <stdint.h>

#define SEQT 512
#define NB   16
#define NT   512

#define S0   448    // layer0 B row stride bytes (K=96 -> 6x64B groups, padded)
#define S1   576    // layer1 B row stride bytes (K=128 -> 8x64B groups, padded)

// dynamic SMEM map (bytes)
#define OFF_B0   0                          // 2 parities x 16*448 = 14336
#define OFF_B1   14336                      // 2 parities x 16*576 = 18432
#define OFF_XA0  32768                      // exchange: 4 regions x 16 warps x 32 lanes x 16B
#define OFF_XB0  40960
#define OFF_XA1  49152
#define OFF_XB1  57344
#define SMEM_TOTAL 65536

__device__ __forceinline__ void mma_f16(float c[4], const uint32_t a[4],
                                        uint32_t b0, uint32_t b1) {
    asm volatile(
        "mma.sync.aligned.m16n8k16.row.col.f32.f16.f16.f32 "
        "{%0,%1,%2,%3}, {%4,%5,%6,%7}, {%8,%9}, {%0,%1,%2,%3};"
        : "+f"(c[0]), "+f"(c[1]), "+f"(c[2]), "+f"(c[3])
        : "r"(a[0]), "r"(a[1]), "r"(a[2]), "r"(a[3]), "r"(b0), "r"(b1));
}

__device__ __forceinline__ void split_f16(float v, uint16_t& hi, uint16_t& lo) {
    __half h = __float2half_rn(v);
    __half l = __float2half_rn(v - __half2float(h));
    hi = __half_as_ushort(h);
    lo = __half_as_ushort(l);
}

__device__ __forceinline__ float ex2f(float v) { float r; asm("ex2.approx.f32 %0, %1;" : "=f"(r) : "f"(v)); return r; }
__device__ __forceinline__ float rcpf(float v) { float r; asm("rcp.approx.f32 %0, %1;" : "=f"(r) : "f"(v)); return r; }
__device__ __forceinline__ float sigf(float x)   { return rcpf(1.0f + ex2f(-1.442695041f * x)); }
__device__ __forceinline__ float tanhf_(float x) { return fmaf(2.0f, rcpf(1.0f + ex2f(-2.885390082f * x)), -1.0f); }

// byte offset of (batch n, k) in hi/lo-interleaved B buffer
__device__ __forceinline__ int boff(int n, int k, int S) {
    int r = k & 15;
    return n * S + (k >> 4) * 64 + ((r >> 1) & 3) * 16 + ((r >> 3) << 2) + ((r & 1) << 1);
}

__global__ void __launch_bounds__(NT, 1)
lstm_fused(const float* __restrict__ x,
           const float* __restrict__ W_ih0, const float* __restrict__ W_hh0,
           const float* __restrict__ b_ih0, const float* __restrict__ b_hh0,
           const float* __restrict__ W_ih1, const float* __restrict__ W_hh1,
           const float* __restrict__ b_ih1, const float* __restrict__ b_hh1,
           const float* __restrict__ ln_g, const float* __restrict__ ln_b,
           const float* __restrict__ fc_w, const float* __restrict__ fc_b,
           float* __restrict__ out)
{
    extern __shared__ __align__(16) unsigned char sm[];
    const int tid  = threadIdx.x;
    const int w    = tid >> 5;
    const int lane = tid & 31;
    const int g    = lane >> 2;
    const int tq   = lane & 3;
    const int wp   = w & 7;          // pair id (j-block)
    const int s    = w >> 3;         // K-half this warp computes; batch-half it updates
    const int jv   = 8 * wp + g;     // cell index this thread owns
    const int b0   = blockIdx.x * NB;

    // zero B buffers
    for (int i = tid; i < 32768 / 4; i += NT) ((uint32_t*)sm)[i] = 0;

    // ---- A fragments: BOTH gate tiles, K-half s, fp16 (regs only) ----
    uint32_t A0[2][3][4], A1[2][4][4];
    #pragma unroll
    for (int tile = 0; tile < 2; tile++) {
        #pragma unroll
        for (int kt = 0; kt < 3; kt++) {
            #pragma unroll
            for (int i = 0; i < 4; i++) {
                int m = tile * 128 + (i & 1) * 64 + jv;
                int k = 48 * s + 16 * kt + 2 * tq + (i >> 1) * 8;
                float v0 = (k < 32)     ? W_ih0[m * 32 + k]     : W_hh0[m * 64 + k - 32];
                float v1 = (k + 1 < 32) ? W_ih0[m * 32 + k + 1] : W_hh0[m * 64 + k + 1 - 32];
                uint16_t h0 = __half_as_ushort(__float2half_rn(v0));
                uint16_t h1 = __half_as_ushort(__float2half_rn(v1));
                A0[tile][kt][i] = (uint32_t)h0 | ((uint32_t)h1 << 16);
            }
        }
        #pragma unroll
        for (int kt = 0; kt < 4; kt++) {
            #pragma unroll
            for (int i = 0; i < 4; i++) {
                int m = tile * 128 + (i & 1) * 64 + jv;
                int k = 64 * s + 16 * kt + 2 * tq + (i >> 1) * 8;
                float v0 = (k < 64)     ? W_ih1[m * 64 + k]     : W_hh1[m * 64 + k - 64];
                float v1 = (k + 1 < 64) ? W_ih1[m * 64 + k + 1] : W_hh1[m * 64 + k + 1 - 64];
                uint16_t h0 = __half_as_ushort(__float2half_rn(v0));
                uint16_t h1 = __half_as_ushort(__float2half_rn(v1));
                A1[tile][kt][i] = (uint32_t)h0 | ((uint32_t)h1 << 16);
            }
        }
    }

    float bias0[4], bias1[4];
    #pragma unroll
    for (int q = 0; q < 4; q++) {
        bias0[q] = b_ih0[q * 64 + jv] + b_hh0[q * 64 + jv];
        bias1[q] = b_ih1[q * 64 + jv] + b_hh1[q * 64 + jv];
    }

    // x(0) -> B0 parity 0
    {
        float xv = x[((size_t)(b0 + w) * SEQT) * 32 + lane];
        uint16_t hh, hl; split_f16(xv, hh, hl);
        int o = boff(w, lane, S0);
        *(uint16_t*)(sm + OFF_B0 + o)     = hh;
        *(uint16_t*)(sm + OFF_B0 + o + 8) = hl;
    }
    __syncthreads();

    const int xsl = w * 512 + lane * 16;
    const int psl = (w ^ 8) * 512 + lane * 16;
    float c0s[2] = {0, 0}, c1s[2] = {0, 0}, h1fin[2] = {0, 0};

    #pragma unroll 1
    for (int p = 0; p <= SEQT; p++) {
        const int par = p & 1;
        const unsigned char* B0r = sm + OFF_B0 + par * (NB * S0);
        const unsigned char* B1r = sm + OFF_B1 + par * (NB * S1);
        unsigned char* B0w = sm + OFF_B0 + (par ^ 1) * (NB * S0);
        unsigned char* B1w = sm + OFF_B1 + (par ^ 1) * (NB * S1);

        float xn = 0.0f;
        if (p + 1 < SEQT)
            xn = x[((size_t)(b0 + w) * SEQT + (p + 1)) * 32 + lane];

        // ===== layer0 MMA (K-half s); export partner's batch-half, keep mine =====
        // All C extraction uses constant indices + SEL on s (no dynamic indexing -> no spill).
        float k0A[4], k0B[4];     // kept partials, gates {i,f} / {g,o}
        if (p < SEQT) {
            float C[2][2][4] = {};
            #pragma unroll
            for (int kt = 0; kt < 3; kt++) {
                #pragma unroll
                for (int nt = 0; nt < 2; nt++) {
                    uint4 v = *(const uint4*)(B0r + (8 * nt + g) * S0 + (3 * s + kt) * 64 + tq * 16);
                    mma_f16(C[0][nt], A0[0][kt], v.x, v.y);
                    mma_f16(C[0][nt], A0[0][kt], v.z, v.w);
                    mma_f16(C[1][nt], A0[1][kt], v.x, v.y);
                    mma_f16(C[1][nt], A0[1][kt], v.z, v.w);
                }
            }
            float eA[4], eB[4];
            #pragma unroll
            for (int i = 0; i < 4; i++) {
                eA[i]  = s ? C[0][0][i] : C[0][1][i];   // export half s^1
                eB[i]  = s ? C[1][0][i] : C[1][1][i];
                k0A[i] = s ? C[0][1][i] : C[0][0][i];   // keep half s
                k0B[i] = s ? C[1][1][i] : C[1][0][i];
            }
            *(float4*)(sm + OFF_XA0 + xsl) = make_float4(eA[0], eA[1], eA[2], eA[3]);
            *(float4*)(sm + OFF_XB0 + xsl) = make_float4(eB[0], eB[1], eB[2], eB[3]);
        }

        // ===== layer1 MMA (K-half s) + export =====
        float k1A[4], k1B[4];
        if (p >= 1) {
            float C[2][2][4] = {};
            #pragma unroll
            for (int kt = 0; kt < 4; kt++) {
                #pragma unroll
                for (int nt = 0; nt < 2; nt++) {
                    uint4 v = *(const uint4*)(B1r + (8 * nt + g) * S1 + (4 * s + kt) * 64 + tq * 16);
                    mma_f16(C[0][nt], A1[0][kt], v.x, v.y);
                    mma_f16(C[0][nt], A1[0][kt], v.z, v.w);
                    mma_f16(C[1][nt], A1[1][kt], v.x, v.y);
                    mma_f16(C[1][nt], A1[1][kt], v.z, v.w);
                }
            }
            float eA[4], eB[4];
            #pragma unroll
            for (int i = 0; i < 4; i++) {
                eA[i]  = s ? C[0][0][i] : C[0][1][i];
                eB[i]  = s ? C[1][0][i] : C[1][1][i];
                k1A[i] = s ? C[0][1][i] : C[0][0][i];
                k1B[i] = s ? C[1][1][i] : C[1][0][i];
            }
            *(float4*)(sm + OFF_XA1 + xsl) = make_float4(eA[0], eA[1], eA[2], eA[3]);
            *(float4*)(sm + OFF_XB1 + xsl) = make_float4(eB[0], eB[1], eB[2], eB[3]);
        }

        asm volatile("bar.sync %0, 64;" :: "r"(1 + wp) : "memory");

        // ===== layer0 combine + activate + update =====
        if (p < SEQT) {
            float4 rA = *(const float4*)(sm + OFF_XA0 + psl);
            float4 rB = *(const float4*)(sm + OFF_XB0 + psl);
            float fa[4] = {rA.x, rA.y, rA.z, rA.w};
            float fb[4] = {rB.x, rB.y, rB.z, rB.w};
            #pragma unroll
            for (int d = 0; d < 2; d++) {
                float pi = k0A[d]     + fa[d]     + bias0[0];
                float pf = k0A[2 + d] + fa[2 + d] + bias0[1];
                float pg = k0B[d]     + fb[d]     + bias0[2];
                float po = k0B[2 + d] + fb[2 + d] + bias0[3];
                float ig = sigf(pi), fg = sigf(pf), gg = tanhf_(pg), og = sigf(po);
                float c = fg * c0s[d] + ig * gg;
                c0s[d] = c;
                float h = og * tanhf_(c);
                int b = 8 * s + 2 * tq + d;
                uint16_t hh, hl; split_f16(h, hh, hl);
                int oa = boff(b, 32 + jv, S0);
                *(uint16_t*)(B0w + oa)     = hh;   // layer0 recurrence
                *(uint16_t*)(B0w + oa + 8) = hl;
                int ob = boff(b, jv, S1);
                *(uint16_t*)(B1w + ob)     = hh;   // layer1 input
                *(uint16_t*)(B1w + ob + 8) = hl;
            }
        }

        // ===== layer1 combine + activate + update =====
        if (p >= 1) {
            float4 rA = *(const float4*)(sm + OFF_XA1 + psl);
            float4 rB = *(const float4*)(sm + OFF_XB1 + psl);
            float fa[4] = {rA.x, rA.y, rA.z, rA.w};
            float fb[4] = {rB.x, rB.y, rB.z, rB.w};
            #pragma unroll
            for (int d = 0; d < 2; d++) {
                float pi = k1A[d]     + fa[d]     + bias1[0];
                float pf = k1A[2 + d] + fa[2 + d] + bias1[1];
                float pg = k1B[d]     + fb[d]     + bias1[2];
                float po = k1B[2 + d] + fb[2 + d] + bias1[3];
                float ig = sigf(pi), fg = sigf(pf), gg = tanhf_(pg), og = sigf(po);
                float c = fg * c1s[d] + ig * gg;
                c1s[d] = c;
                float h = og * tanhf_(c);
                h1fin[d] = h;
                int b = 8 * s + 2 * tq + d;
                uint16_t hh, hl; split_f16(h, hh, hl);
                int oc = boff(b, 64 + jv, S1);
                *(uint16_t*)(B1w + oc)     = hh;   // layer1 recurrence
                *(uint16_t*)(B1w + oc + 8) = hl;
            }
        }

        if (p + 1 < SEQT) {
            uint16_t hh, hl; split_f16(xn, hh, hl);
            int o = boff(w, lane, S0);
            *(uint16_t*)(B0w + o)     = hh;
            *(uint16_t*)(B0w + o + 8) = hl;
        }
        __syncthreads();
    }

    // ---- LayerNorm + FC on h1(T-1) ----
    float* hb = (float*)(sm + OFF_XA0);
    #pragma unroll
    for (int d = 0; d < 2; d++) {
        int b = 8 * s + 2 * tq + d;
        hb[b * 64 + jv] = h1fin[d];
    }
    __syncthreads();
    if (tid < NB) {
        const float* h = hb + tid * 64;
        float mu = 0.0f;
        #pragma unroll
        for (int j = 0; j < 64; j++) mu += h[j];
        mu *= (1.0f / 64.0f);
        float var = 0.0f;
        #pragma unroll
        for (int j = 0; j < 64; j++) { float dd = h[j] - mu; var += dd * dd; }
        var *= (1.0f / 64.0f);
        float rstd = rsqrtf(var + 1e-5f);
        float sacc = 0.0f;
        #pragma unroll
        for (int j = 0; j < 64; j++)
            sacc += ((h[j] - mu) * rstd * ln_g[j] + ln_b[j]) * fc_w[j];
        out[b0 + tid] = sacc + fc_b[0];
    }
}

extern "C" void kernel_launch(void* const* d_in, const int* in_sizes, int n_in,
                              void* d_out, int out_size)
{
    const float* x     = (const float*)d_in[0];
    const float* W_ih0 = (const float*)d_in[1];
    const float* W_hh0 = (const float*)d_in[2];
    const float* b_ih0 = (const float*)d_in[3];
    const float* b_hh0 = (const float*)d_in[4];
    const float* W_ih1 = (const float*)d_in[5];
    const float* W_hh1 = (const float*)d_in[6];
    const float* b_ih1 = (const float*)d_in[7];
    const float* b_hh1 = (const float*)d_in[8];
    const float* ln_g  = (const float*)d_in[9];
    const float* ln_b  = (const float*)d_in[10];
    const float* fc_w  = (const float*)d_in[11];
    const float* fc_b  = (const float*)d_in[12];
    float* out = (float*)d_out;

    cudaFuncSetAttribute(lstm_fused, cudaFuncAttributeMaxDynamicSharedMemorySize, SMEM_TOTAL);
    lstm_fused<<<2048 / NB, NT, SMEM_TOTAL>>>(x, W_ih0, W_hh0, b_ih0, b_hh0,
                                              W_ih1, W_hh1, b_ih1, b_hh1,
                                              ln_g, ln_b, fc_w, fc_b, out);
}

// round 10
// speedup vs baseline: 2.4872x; 1.4335x over previous
#include <cuda_runtime.h>
#include <cuda_fp16.h>
#include <stdint.h>

#define SEQT 512
#define NB   16
#define NT   512

#define S0   224    // layer0 B row stride bytes (K=96 -> 6x32B groups + pad)
#define S1   288    // layer1 B row stride bytes (K=128 -> 8x32B groups + pad)

// dynamic SMEM map (bytes)
#define OFF_B0   0                          // 2 parities x 16*224 = 7168
#define OFF_B1   7168                       // 2 parities x 16*288 = 9216
#define OFF_XA0  16384                      // exchange: 4 regions x 16 warps x 32 lanes x 16B
#define OFF_XB0  24576
#define OFF_XA1  32768
#define OFF_XB1  40960
#define SMEM_TOTAL 49152

__device__ __forceinline__ void mma_f16(float c[4], const uint32_t a[4],
                                        uint32_t b0, uint32_t b1) {
    asm volatile(
        "mma.sync.aligned.m16n8k16.row.col.f32.f16.f16.f32 "
        "{%0,%1,%2,%3}, {%4,%5,%6,%7}, {%8,%9}, {%0,%1,%2,%3};"
        : "+f"(c[0]), "+f"(c[1]), "+f"(c[2]), "+f"(c[3])
        : "r"(a[0]), "r"(a[1]), "r"(a[2]), "r"(a[3]), "r"(b0), "r"(b1));
}

__device__ __forceinline__ float ex2f(float v) { float r; asm("ex2.approx.f32 %0, %1;" : "=f"(r) : "f"(v)); return r; }
__device__ __forceinline__ float rcpf(float v) { float r; asm("rcp.approx.f32 %0, %1;" : "=f"(r) : "f"(v)); return r; }
__device__ __forceinline__ float sigf(float x)   { return rcpf(1.0f + ex2f(-1.442695041f * x)); }
__device__ __forceinline__ float tanhf_(float x) { return fmaf(2.0f, rcpf(1.0f + ex2f(-2.885390082f * x)), -1.0f); }

// byte offset of (batch n, k) in fp16 B buffer
// 32B group per 16 k; 8B unit per tq: [k(2t), k(2t+1), k(2t+8), k(2t+9)]
__device__ __forceinline__ int boff(int n, int k, int S) {
    return n * S + (k >> 4) * 32 + ((k >> 1) & 3) * 8 + ((k >> 3) & 1) * 4 + (k & 1) * 2;
}

__global__ void __launch_bounds__(NT, 1)
lstm_fused(const float* __restrict__ x,
           const float* __restrict__ W_ih0, const float* __restrict__ W_hh0,
           const float* __restrict__ b_ih0, const float* __restrict__ b_hh0,
           const float* __restrict__ W_ih1, const float* __restrict__ W_hh1,
           const float* __restrict__ b_ih1, const float* __restrict__ b_hh1,
           const float* __restrict__ ln_g, const float* __restrict__ ln_b,
           const float* __restrict__ fc_w, const float* __restrict__ fc_b,
           float* __restrict__ out)
{
    extern __shared__ __align__(16) unsigned char sm[];
    const int tid  = threadIdx.x;
    const int w    = tid >> 5;
    const int lane = tid & 31;
    const int g    = lane >> 2;
    const int tq   = lane & 3;
    const int wp   = w & 7;          // pair id (j-block)
    const int s    = w >> 3;         // K-half this warp computes; batch-half it updates
    const int jv   = 8 * wp + g;     // cell index this thread owns
    const int b0   = blockIdx.x * NB;

    // zero B buffers
    for (int i = tid; i < OFF_XA0 / 4; i += NT) ((uint32_t*)sm)[i] = 0;

    // ---- A fragments: BOTH gate tiles, K-half s, fp16 (regs only) ----
    uint32_t A0[2][3][4], A1[2][4][4];
    #pragma unroll
    for (int tile = 0; tile < 2; tile++) {
        #pragma unroll
        for (int kt = 0; kt < 3; kt++) {
            #pragma unroll
            for (int i = 0; i < 4; i++) {
                int m = tile * 128 + (i & 1) * 64 + jv;
                int k = 48 * s + 16 * kt + 2 * tq + (i >> 1) * 8;
                float v0 = (k < 32)     ? W_ih0[m * 32 + k]     : W_hh0[m * 64 + k - 32];
                float v1 = (k + 1 < 32) ? W_ih0[m * 32 + k + 1] : W_hh0[m * 64 + k + 1 - 32];
                uint16_t h0 = __half_as_ushort(__float2half_rn(v0));
                uint16_t h1 = __half_as_ushort(__float2half_rn(v1));
                A0[tile][kt][i] = (uint32_t)h0 | ((uint32_t)h1 << 16);
            }
        }
        #pragma unroll
        for (int kt = 0; kt < 4; kt++) {
            #pragma unroll
            for (int i = 0; i < 4; i++) {
                int m = tile * 128 + (i & 1) * 64 + jv;
                int k = 64 * s + 16 * kt + 2 * tq + (i >> 1) * 8;
                float v0 = (k < 64)     ? W_ih1[m * 64 + k]     : W_hh1[m * 64 + k - 64];
                float v1 = (k + 1 < 64) ? W_ih1[m * 64 + k + 1] : W_hh1[m * 64 + k + 1 - 64];
                uint16_t h0 = __half_as_ushort(__float2half_rn(v0));
                uint16_t h1 = __half_as_ushort(__float2half_rn(v1));
                A1[tile][kt][i] = (uint32_t)h0 | ((uint32_t)h1 << 16);
            }
        }
    }

    float bias0[4], bias1[4];
    #pragma unroll
    for (int q = 0; q < 4; q++) {
        bias0[q] = b_ih0[q * 64 + jv] + b_hh0[q * 64 + jv];
        bias1[q] = b_ih1[q * 64 + jv] + b_hh1[q * 64 + jv];
    }

    // x(0) -> B0 parity 0 (warp = batch row, lane = k)
    {
        float xv = x[((size_t)(b0 + w) * SEQT) * 32 + lane];
        *(uint16_t*)(sm + OFF_B0 + boff(w, lane, S0)) =
            __half_as_ushort(__float2half_rn(xv));
    }
    __syncthreads();

    const int xsl = w * 512 + lane * 16;
    const int psl = (w ^ 8) * 512 + lane * 16;
    float c0s[2] = {0, 0}, c1s[2] = {0, 0}, h1fin[2] = {0, 0};

    #pragma unroll 1
    for (int p = 0; p <= SEQT; p++) {
        const int par = p & 1;
        const unsigned char* B0r = sm + OFF_B0 + par * (NB * S0);
        const unsigned char* B1r = sm + OFF_B1 + par * (NB * S1);
        unsigned char* B0w = sm + OFF_B0 + (par ^ 1) * (NB * S0);
        unsigned char* B1w = sm + OFF_B1 + (par ^ 1) * (NB * S1);

        float xn = 0.0f;
        if (p + 1 < SEQT)
            xn = x[((size_t)(b0 + w) * SEQT + (p + 1)) * 32 + lane];

        // ===== layer0 MMA (K-half s); export partner's batch-half, keep mine =====
        float k0A[4], k0B[4];     // kept partials, gates {i,f} / {g,o}
        if (p < SEQT) {
            float C[2][2][4] = {};
            #pragma unroll
            for (int kt = 0; kt < 3; kt++) {
                #pragma unroll
                for (int nt = 0; nt < 2; nt++) {
                    uint2 v = *(const uint2*)(B0r + (8 * nt + g) * S0 + (3 * s + kt) * 32 + tq * 8);
                    mma_f16(C[0][nt], A0[0][kt], v.x, v.y);
                    mma_f16(C[1][nt], A0[1][kt], v.x, v.y);
                }
            }
            float eA[4], eB[4];
            #pragma unroll
            for (int i = 0; i < 4; i++) {
                eA[i]  = s ? C[0][0][i] : C[0][1][i];   // export half s^1
                eB[i]  = s ? C[1][0][i] : C[1][1][i];
                k0A[i] = s ? C[0][1][i] : C[0][0][i];   // keep half s
                k0B[i] = s ? C[1][1][i] : C[1][0][i];
            }
            *(float4*)(sm + OFF_XA0 + xsl) = make_float4(eA[0], eA[1], eA[2], eA[3]);
            *(float4*)(sm + OFF_XB0 + xsl) = make_float4(eB[0], eB[1], eB[2], eB[3]);
        }

        // ===== layer1 MMA (K-half s) + export =====
        float k1A[4], k1B[4];
        if (p >= 1) {
            float C[2][2][4] = {};
            #pragma unroll
            for (int kt = 0; kt < 4; kt++) {
                #pragma unroll
                for (int nt = 0; nt < 2; nt++) {
                    uint2 v = *(const uint2*)(B1r + (8 * nt + g) * S1 + (4 * s + kt) * 32 + tq * 8);
                    mma_f16(C[0][nt], A1[0][kt], v.x, v.y);
                    mma_f16(C[1][nt], A1[1][kt], v.x, v.y);
                }
            }
            float eA[4], eB[4];
            #pragma unroll
            for (int i = 0; i < 4; i++) {
                eA[i]  = s ? C[0][0][i] : C[0][1][i];
                eB[i]  = s ? C[1][0][i] : C[1][1][i];
                k1A[i] = s ? C[0][1][i] : C[0][0][i];
                k1B[i] = s ? C[1][1][i] : C[1][0][i];
            }
            *(float4*)(sm + OFF_XA1 + xsl) = make_float4(eA[0], eA[1], eA[2], eA[3]);
            *(float4*)(sm + OFF_XB1 + xsl) = make_float4(eB[0], eB[1], eB[2], eB[3]);
        }

        asm volatile("bar.sync %0, 64;" :: "r"(1 + wp) : "memory");

        // ===== layer0 combine + activate + update =====
        if (p < SEQT) {
            float4 rA = *(const float4*)(sm + OFF_XA0 + psl);
            float4 rB = *(const float4*)(sm + OFF_XB0 + psl);
            float fa[4] = {rA.x, rA.y, rA.z, rA.w};
            float fb[4] = {rB.x, rB.y, rB.z, rB.w};
            #pragma unroll
            for (int d = 0; d < 2; d++) {
                float pi = k0A[d]     + fa[d]     + bias0[0];
                float pf = k0A[2 + d] + fa[2 + d] + bias0[1];
                float pg = k0B[d]     + fb[d]     + bias0[2];
                float po = k0B[2 + d] + fb[2 + d] + bias0[3];
                float ig = sigf(pi), fg = sigf(pf), gg = tanhf_(pg), og = sigf(po);
                float c = fg * c0s[d] + ig * gg;
                c0s[d] = c;
                float h = og * tanhf_(c);
                int b = 8 * s + 2 * tq + d;
                uint16_t hh = __half_as_ushort(__float2half_rn(h));
                *(uint16_t*)(B0w + boff(b, 32 + jv, S0)) = hh;   // layer0 recurrence
                *(uint16_t*)(B1w + boff(b, jv, S1))      = hh;   // layer1 input
            }
        }

        // ===== layer1 combine + activate + update =====
        if (p >= 1) {
            float4 rA = *(const float4*)(sm + OFF_XA1 + psl);
            float4 rB = *(const float4*)(sm + OFF_XB1 + psl);
            float fa[4] = {rA.x, rA.y, rA.z, rA.w};
            float fb[4] = {rB.x, rB.y, rB.z, rB.w};
            #pragma unroll
            for (int d = 0; d < 2; d++) {
                float pi = k1A[d]     + fa[d]     + bias1[0];
                float pf = k1A[2 + d] + fa[2 + d] + bias1[1];
                float pg = k1B[d]     + fb[d]     + bias1[2];
                float po = k1B[2 + d] + fb[2 + d] + bias1[3];
                float ig = sigf(pi), fg = sigf(pf), gg = tanhf_(pg), og = sigf(po);
                float c = fg * c1s[d] + ig * gg;
                c1s[d] = c;
                float h = og * tanhf_(c);
                h1fin[d] = h;
                int b = 8 * s + 2 * tq + d;
                uint16_t hh = __half_as_ushort(__float2half_rn(h));
                *(uint16_t*)(B1w + boff(b, 64 + jv, S1)) = hh;   // layer1 recurrence
            }
        }

        if (p + 1 < SEQT) {
            *(uint16_t*)(B0w + boff(w, lane, S0)) =
                __half_as_ushort(__float2half_rn(xn));
        }
        __syncthreads();
    }

    // ---- LayerNorm + FC on h1(T-1) ----
    float* hb = (float*)(sm + OFF_XA0);
    #pragma unroll
    for (int d = 0; d < 2; d++) {
        int b = 8 * s + 2 * tq + d;
        hb[b * 64 + jv] = h1fin[d];
    }
    __syncthreads();
    if (tid < NB) {
        const float* h = hb + tid * 64;
        float mu = 0.0f;
        #pragma unroll
        for (int j = 0; j < 64; j++) mu += h[j];
        mu *= (1.0f / 64.0f);
        float var = 0.0f;
        #pragma unroll
        for (int j = 0; j < 64; j++) { float dd = h[j] - mu; var += dd * dd; }
        var *= (1.0f / 64.0f);
        float rstd = rsqrtf(var + 1e-5f);
        float sacc = 0.0f;
        #pragma unroll
        for (int j = 0; j < 64; j++)
            sacc += ((h[j] - mu) * rstd * ln_g[j] + ln_b[j]) * fc_w[j];
        out[b0 + tid] = sacc + fc_b[0];
    }
}

extern "C" void kernel_launch(void* const* d_in, const int* in_sizes, int n_in,
                              void* d_out, int out_size)
{
    const float* x     = (const float*)d_in[0];
    const float* W_ih0 = (const float*)d_in[1];
    const float* W_hh0 = (const float*)d_in[2];
    const float* b_ih0 = (const float*)d_in[3];
    const float* b_hh0 = (const float*)d_in[4];
    const float* W_ih1 = (const float*)d_in[5];
    const float* W_hh1 = (const float*)d_in[6];
    const float* b_ih1 = (const float*)d_in[7];
    const float* b_hh1 = (const float*)d_in[8];
    const float* ln_g  = (const float*)d_in[9];
    const float* ln_b  = (const float*)d_in[10];
    const float* fc_w  = (const float*)d_in[11];
    const float* fc_b  = (const float*)d_in[12];
    float* out = (float*)d_out;

    cudaFuncSetAttribute(lstm_fused, cudaFuncAttributeMaxDynamicSharedMemorySize, SMEM_TOTAL);
    lstm_fused<<<2048 / NB, NT, SMEM_TOTAL>>>(x, W_ih0, W_hh0, b_ih0, b_hh0,
                                              W_ih1, W_hh1, b_ih1, b_hh1,
                                              ln_g, ln_b, fc_w, fc_b, out);
}

// round 11
// speedup vs baseline: 2.7800x; 1.1177x over previous
#include <cuda_runtime.h>
#include <cuda_fp16.h>
#include <stdint.h>

#define SEQT 512
#define NB   16
#define NT   512

#define S0   224    // layer0 B row stride bytes (K=96 -> 6x32B groups + pad)
#define S1   288    // layer1 B row stride bytes (K=128 -> 8x32B groups + pad)

// dynamic SMEM map (bytes)
#define OFF_B0   0                          // 2 parities x 16*224 = 7168
#define OFF_B1   7168                       // 2 parities x 16*288 = 9216
#define OFF_XA0  16384                      // exchange: 4 regions x 16 warps x 32 lanes x 16B
#define OFF_XB0  24576
#define OFF_XA1  32768
#define OFF_XB1  40960
#define SMEM_TOTAL 49152

__device__ __forceinline__ void mma_f16(float c[4], const uint32_t a[4],
                                        uint32_t b0, uint32_t b1) {
    asm volatile(
        "mma.sync.aligned.m16n8k16.row.col.f32.f16.f16.f32 "
        "{%0,%1,%2,%3}, {%4,%5,%6,%7}, {%8,%9}, {%0,%1,%2,%3};"
        : "+f"(c[0]), "+f"(c[1]), "+f"(c[2]), "+f"(c[3])
        : "r"(a[0]), "r"(a[1]), "r"(a[2]), "r"(a[3]), "r"(b0), "r"(b1));
}

__device__ __forceinline__ float tanha(float x) {
    float r; asm("tanh.approx.f32 %0, %1;" : "=f"(r) : "f"(x)); return r;
}
__device__ __forceinline__ float sigf(float x)   { return fmaf(tanha(0.5f * x), 0.5f, 0.5f); }
__device__ __forceinline__ float tanhf_(float x) { return tanha(x); }

// byte offset of (batch n, k) in fp16 B buffer
// 32B group per 16 k; 8B unit per tq: [k(2t), k(2t+1), k(2t+8), k(2t+9)]
__device__ __forceinline__ int boff(int n, int k, int S) {
    return n * S + (k >> 4) * 32 + ((k >> 1) & 3) * 8 + ((k >> 3) & 1) * 4 + (k & 1) * 2;
}

__global__ void __launch_bounds__(NT, 1)
lstm_fused(const float* __restrict__ x,
           const float* __restrict__ W_ih0, const float* __restrict__ W_hh0,
           const float* __restrict__ b_ih0, const float* __restrict__ b_hh0,
           const float* __restrict__ W_ih1, const float* __restrict__ W_hh1,
           const float* __restrict__ b_ih1, const float* __restrict__ b_hh1,
           const float* __restrict__ ln_g, const float* __restrict__ ln_b,
           const float* __restrict__ fc_w, const float* __restrict__ fc_b,
           float* __restrict__ out)
{
    extern __shared__ __align__(16) unsigned char sm[];
    const int tid  = threadIdx.x;
    const int w    = tid >> 5;
    const int lane = tid & 31;
    const int g    = lane >> 2;
    const int tq   = lane & 3;
    const int wp   = w & 7;          // pair id (j-block)
    const int s    = w >> 3;         // K-half this warp computes; batch-half it updates
    const int jv   = 8 * wp + g;     // cell index this thread owns
    const int b0   = blockIdx.x * NB;

    // zero B buffers
    for (int i = tid; i < OFF_XA0 / 4; i += NT) ((uint32_t*)sm)[i] = 0;

    // ---- A fragments: BOTH gate tiles, K-half s, fp16 (regs only) ----
    uint32_t A0[2][3][4], A1[2][4][4];
    #pragma unroll
    for (int tile = 0; tile < 2; tile++) {
        #pragma unroll
        for (int kt = 0; kt < 3; kt++) {
            #pragma unroll
            for (int i = 0; i < 4; i++) {
                int m = tile * 128 + (i & 1) * 64 + jv;
                int k = 48 * s + 16 * kt + 2 * tq + (i >> 1) * 8;
                float v0 = (k < 32)     ? W_ih0[m * 32 + k]     : W_hh0[m * 64 + k - 32];
                float v1 = (k + 1 < 32) ? W_ih0[m * 32 + k + 1] : W_hh0[m * 64 + k + 1 - 32];
                uint16_t h0 = __half_as_ushort(__float2half_rn(v0));
                uint16_t h1 = __half_as_ushort(__float2half_rn(v1));
                A0[tile][kt][i] = (uint32_t)h0 | ((uint32_t)h1 << 16);
            }
        }
        #pragma unroll
        for (int kt = 0; kt < 4; kt++) {
            #pragma unroll
            for (int i = 0; i < 4; i++) {
                int m = tile * 128 + (i & 1) * 64 + jv;
                int k = 64 * s + 16 * kt + 2 * tq + (i >> 1) * 8;
                float v0 = (k < 64)     ? W_ih1[m * 64 + k]     : W_hh1[m * 64 + k - 64];
                float v1 = (k + 1 < 64) ? W_ih1[m * 64 + k + 1] : W_hh1[m * 64 + k + 1 - 64];
                uint16_t h0 = __half_as_ushort(__float2half_rn(v0));
                uint16_t h1 = __half_as_ushort(__float2half_rn(v1));
                A1[tile][kt][i] = (uint32_t)h0 | ((uint32_t)h1 << 16);
            }
        }
    }

    float bias0[4], bias1[4];
    #pragma unroll
    for (int q = 0; q < 4; q++) {
        bias0[q] = b_ih0[q * 64 + jv] + b_hh0[q * 64 + jv];
        bias1[q] = b_ih1[q * 64 + jv] + b_hh1[q * 64 + jv];
    }

    // x(0) -> B0 parity 0 (warp = batch row, lane = k)
    {
        float xv = x[((size_t)(b0 + w) * SEQT) * 32 + lane];
        *(uint16_t*)(sm + OFF_B0 + boff(w, lane, S0)) =
            __half_as_ushort(__float2half_rn(xv));
    }
    __syncthreads();

    const int xsl = w * 512 + lane * 16;
    const int psl = (w ^ 8) * 512 + lane * 16;
    float c0s[2] = {0, 0}, c1s[2] = {0, 0}, h1fin[2] = {0, 0};

    // ---------- phase bodies as lambdas (identical codegen everywhere) ----------
    auto l0_mma = [&](const unsigned char* B0r, float k0A[4], float k0B[4]) {
        float C[2][2][4] = {};
        #pragma unroll
        for (int kt = 0; kt < 3; kt++) {
            #pragma unroll
            for (int nt = 0; nt < 2; nt++) {
                uint2 v = *(const uint2*)(B0r + (8 * nt + g) * S0 + (3 * s + kt) * 32 + tq * 8);
                mma_f16(C[0][nt], A0[0][kt], v.x, v.y);
                mma_f16(C[1][nt], A0[1][kt], v.x, v.y);
            }
        }
        float eA[4], eB[4];
        #pragma unroll
        for (int i = 0; i < 4; i++) {
            eA[i]  = s ? C[0][0][i] : C[0][1][i];
            eB[i]  = s ? C[1][0][i] : C[1][1][i];
            k0A[i] = s ? C[0][1][i] : C[0][0][i];
            k0B[i] = s ? C[1][1][i] : C[1][0][i];
        }
        *(float4*)(sm + OFF_XA0 + xsl) = make_float4(eA[0], eA[1], eA[2], eA[3]);
        *(float4*)(sm + OFF_XB0 + xsl) = make_float4(eB[0], eB[1], eB[2], eB[3]);
    };
    auto l1_mma = [&](const unsigned char* B1r, float k1A[4], float k1B[4]) {
        float C[2][2][4] = {};
        #pragma unroll
        for (int kt = 0; kt < 4; kt++) {
            #pragma unroll
            for (int nt = 0; nt < 2; nt++) {
                uint2 v = *(const uint2*)(B1r + (8 * nt + g) * S1 + (4 * s + kt) * 32 + tq * 8);
                mma_f16(C[0][nt], A1[0][kt], v.x, v.y);
                mma_f16(C[1][nt], A1[1][kt], v.x, v.y);
            }
        }
        float eA[4], eB[4];
        #pragma unroll
        for (int i = 0; i < 4; i++) {
            eA[i]  = s ? C[0][0][i] : C[0][1][i];
            eB[i]  = s ? C[1][0][i] : C[1][1][i];
            k1A[i] = s ? C[0][1][i] : C[0][0][i];
            k1B[i] = s ? C[1][1][i] : C[1][0][i];
        }
        *(float4*)(sm + OFF_XA1 + xsl) = make_float4(eA[0], eA[1], eA[2], eA[3]);
        *(float4*)(sm + OFF_XB1 + xsl) = make_float4(eB[0], eB[1], eB[2], eB[3]);
    };
    auto l0_upd = [&](const float k0A[4], const float k0B[4],
                      unsigned char* B0w, unsigned char* B1w) {
        float4 rA = *(const float4*)(sm + OFF_XA0 + psl);
        float4 rB = *(const float4*)(sm + OFF_XB0 + psl);
        float fa[4] = {rA.x, rA.y, rA.z, rA.w};
        float fb[4] = {rB.x, rB.y, rB.z, rB.w};
        #pragma unroll
        for (int d = 0; d < 2; d++) {
            float pi = k0A[d]     + fa[d]     + bias0[0];
            float pf = k0A[2 + d] + fa[2 + d] + bias0[1];
            float pg = k0B[d]     + fb[d]     + bias0[2];
            float po = k0B[2 + d] + fb[2 + d] + bias0[3];
            float ig = sigf(pi), fg = sigf(pf), gg = tanhf_(pg), og = sigf(po);
            float c = fg * c0s[d] + ig * gg;
            c0s[d] = c;
            float h = og * tanhf_(c);
            int b = 8 * s + 2 * tq + d;
            uint16_t hh = __half_as_ushort(__float2half_rn(h));
            *(uint16_t*)(B0w + boff(b, 32 + jv, S0)) = hh;
            *(uint16_t*)(B1w + boff(b, jv, S1))      = hh;
        }
    };
    auto l1_upd = [&](const float k1A[4], const float k1B[4], unsigned char* B1w) {
        float4 rA = *(const float4*)(sm + OFF_XA1 + psl);
        float4 rB = *(const float4*)(sm + OFF_XB1 + psl);
        float fa[4] = {rA.x, rA.y, rA.z, rA.w};
        float fb[4] = {rB.x, rB.y, rB.z, rB.w};
        #pragma unroll
        for (int d = 0; d < 2; d++) {
            float pi = k1A[d]     + fa[d]     + bias1[0];
            float pf = k1A[2 + d] + fa[2 + d] + bias1[1];
            float pg = k1B[d]     + fb[d]     + bias1[2];
            float po = k1B[2 + d] + fb[2 + d] + bias1[3];
            float ig = sigf(pi), fg = sigf(pf), gg = tanhf_(pg), og = sigf(po);
            float c = fg * c1s[d] + ig * gg;
            c1s[d] = c;
            float h = og * tanhf_(c);
            h1fin[d] = h;
            int b = 8 * s + 2 * tq + d;
            uint16_t hh = __half_as_ushort(__float2half_rn(h));
            *(uint16_t*)(B1w + boff(b, 64 + jv, S1)) = hh;
        }
    };

    // ---------- p = 0 (layer0 only) ----------
    {
        const unsigned char* B0r = sm + OFF_B0;
        unsigned char* B0w = sm + OFF_B0 + NB * S0;
        unsigned char* B1w = sm + OFF_B1 + NB * S1;
        float xn = x[((size_t)(b0 + w) * SEQT + 1) * 32 + lane];
        float k0A[4], k0B[4];
        l0_mma(B0r, k0A, k0B);
        asm volatile("bar.sync %0, 64;" :: "r"(1 + wp) : "memory");
        l0_upd(k0A, k0B, B0w, B1w);
        *(uint16_t*)(B0w + boff(w, lane, S0)) = __half_as_ushort(__float2half_rn(xn));
        __syncthreads();
    }

    // ---------- main loop p = 1 .. SEQT-1 (both layers, no branches) ----------
    #pragma unroll 1
    for (int p = 1; p < SEQT; p++) {
        const int par = p & 1;
        const unsigned char* B0r = sm + OFF_B0 + par * (NB * S0);
        const unsigned char* B1r = sm + OFF_B1 + par * (NB * S1);
        unsigned char* B0w = sm + OFF_B0 + (par ^ 1) * (NB * S0);
        unsigned char* B1w = sm + OFF_B1 + (par ^ 1) * (NB * S1);

        float xn = 0.0f;
        if (p + 1 < SEQT)
            xn = x[((size_t)(b0 + w) * SEQT + (p + 1)) * 32 + lane];

        float k0A[4], k0B[4], k1A[4], k1B[4];
        l0_mma(B0r, k0A, k0B);
        l1_mma(B1r, k1A, k1B);
        asm volatile("bar.sync %0, 64;" :: "r"(1 + wp) : "memory");
        l0_upd(k0A, k0B, B0w, B1w);
        l1_upd(k1A, k1B, B1w);

        if (p + 1 < SEQT)
            *(uint16_t*)(B0w + boff(w, lane, S0)) = __half_as_ushort(__float2half_rn(xn));
        __syncthreads();
    }

    // ---------- p = SEQT (layer1 only, t = SEQT-1) ----------
    {
        const unsigned char* B1r = sm + OFF_B1;          // parity 0 (SEQT even)
        unsigned char* B1w = sm + OFF_B1 + NB * S1;
        float k1A[4], k1B[4];
        l1_mma(B1r, k1A, k1B);
        asm volatile("bar.sync %0, 64;" :: "r"(1 + wp) : "memory");
        l1_upd(k1A, k1B, B1w);
        __syncthreads();
    }

    // ---- LayerNorm + FC on h1(T-1) ----
    float* hb = (float*)(sm + OFF_XA0);
    #pragma unroll
    for (int d = 0; d < 2; d++) {
        int b = 8 * s + 2 * tq + d;
        hb[b * 64 + jv] = h1fin[d];
    }
    __syncthreads();
    if (tid < NB) {
        const float* h = hb + tid * 64;
        float mu = 0.0f;
        #pragma unroll
        for (int j = 0; j < 64; j++) mu += h[j];
        mu *= (1.0f / 64.0f);
        float var = 0.0f;
        #pragma unroll
        for (int j = 0; j < 64; j++) { float dd = h[j] - mu; var += dd * dd; }
        var *= (1.0f / 64.0f);
        float rstd = rsqrtf(var + 1e-5f);
        float sacc = 0.0f;
        #pragma unroll
        for (int j = 0; j < 64; j++)
            sacc += ((h[j] - mu) * rstd * ln_g[j] + ln_b[j]) * fc_w[j];
        out[b0 + tid] = sacc + fc_b[0];
    }
}

extern "C" void kernel_launch(void* const* d_in, const int* in_sizes, int n_in,
                              void* d_out, int out_size)
{
    const float* x     = (const float*)d_in[0];
    const float* W_ih0 = (const float*)d_in[1];
    const float* W_hh0 = (const float*)d_in[2];
    const float* b_ih0 = (const float*)d_in[3];
    const float* b_hh0 = (const float*)d_in[4];
    const float* W_ih1 = (const float*)d_in[5];
    const float* W_hh1 = (const float*)d_in[6];
    const float* b_ih1 = (const float*)d_in[7];
    const float* b_hh1 = (const float*)d_in[8];
    const float* ln_g  = (const float*)d_in[9];
    const float* ln_b  = (const float*)d_in[10];
    const float* fc_w  = (const float*)d_in[11];
    const float* fc_b  = (const float*)d_in[12];
    float* out = (float*)d_out;

    cudaFuncSetAttribute(lstm_fused, cudaFuncAttributeMaxDynamicSharedMemorySize, SMEM_TOTAL);
    lstm_fused<<<2048 / NB, NT, SMEM_TOTAL>>>(x, W_ih0, W_hh0, b_ih0, b_hh0,
                                              W_ih1, W_hh1, b_ih1, b_hh1,
                                              ln_g, ln_b, fc_w, fc_b, out);
}